// round 16
// baseline (speedup 1.0000x reference)
#include <cuda_runtime.h>
#include <cuda_bf16.h>
#include <cstdint>

#define NQ 2048
#define NK 4096
#define DIMK 1024

// Split-bf16 operand tiles for the main kernel: per (pos, head) one 128B row =
// hi d0..31 | lo d0..31, 16B units permuted u ^= (pos & 7).
__device__ uint4 g_K_sw[NK * 8 * 8];   // (pos*8+head)*8 units
__device__ uint4 g_Q_sw[NQ * 8 * 8];

// Pre-converted projection operands, chunked layout: [chunk 0..31][row][128B row]
__device__ uint4 g_AC[32 * 6144 * 8];   // 25.2 MB
__device__ uint4 g_WC[32 * 512 * 8];    // 2 MB

#define LDSM4(r, addr) \
    asm volatile("ldmatrix.sync.aligned.m8n8.x4.shared.b16 {%0,%1,%2,%3}, [%4];" \
        : "=r"((r)[0]),"=r"((r)[1]),"=r"((r)[2]),"=r"((r)[3]) : "r"(addr))

#define MMA_BF16(accp, a, b0, b1) \
    asm volatile("mma.sync.aligned.m16n8k16.row.col.f32.bf16.bf16.f32 " \
        "{%0,%1,%2,%3}, {%4,%5,%6,%7}, {%8,%9}, {%0,%1,%2,%3};" \
        : "+f"((accp)[0]),"+f"((accp)[1]),"+f"((accp)[2]),"+f"((accp)[3]) \
        : "r"((a)[0]),"r"((a)[1]),"r"((a)[2]),"r"((a)[3]), "r"(b0),"r"(b1))

static __device__ __forceinline__ uint32_t smem_u32(const void* p) {
    uint32_t a;
    asm("{ .reg .u64 t; cvta.to.shared.u64 t, %1; cvt.u32.u64 %0, t; }"
        : "=r"(a) : "l"(p));
    return a;
}

static __device__ __forceinline__ void split2(float f0, float f1,
                                              uint32_t& hv, uint32_t& lv) {
    __nv_bfloat16 h0 = __float2bfloat16(f0);
    __nv_bfloat16 h1 = __float2bfloat16(f1);
    __nv_bfloat16 l0 = __float2bfloat16(f0 - __bfloat162float(h0));
    __nv_bfloat16 l1 = __float2bfloat16(f1 - __bfloat162float(h1));
    hv = (uint32_t)__bfloat16_as_ushort(h0) | ((uint32_t)__bfloat16_as_ushort(h1) << 16);
    lv = (uint32_t)__bfloat16_as_ushort(l0) | ((uint32_t)__bfloat16_as_ushort(l1) << 16);
}

// ---------------------------------------------------------------------------
// Convert kernel (unchanged): fp32 -> bf16 hi|lo split chunks.
// ---------------------------------------------------------------------------
__global__ __launch_bounds__(256) void convert_split(
    const float* __restrict__ Qin, const float* __restrict__ Kin,
    const float* __restrict__ Wq,  const float* __restrict__ Wk)
{
    const int t = blockIdx.x * 256 + threadIdx.x;
    const int r = t >> 7;
    const int rem = t & 127;
    const int ch = rem >> 2;
    const int g  = rem & 3;

    const float* src;
    unsigned char* dstbase;
    int rows, lr;
    if (r < 6144) {
        lr = r;
        src = (r < 2048) ? (Qin + (size_t)r * DIMK)
                         : (Kin + (size_t)(r - 2048) * DIMK);
        dstbase = (unsigned char*)g_AC; rows = 6144;
    } else {
        lr = r - 6144;
        src = (lr < 256) ? (Wq + (size_t)lr * DIMK)
                         : (Wk + (size_t)(lr - 256) * DIMK);
        dstbase = (unsigned char*)g_WC; rows = 512;
    }

    const float* p = src + ch * 32 + g * 8;
    float4 v0 = *(const float4*)p;
    float4 v1 = *(const float4*)(p + 4);

    uint32_t h[4], l[4];
    split2(v0.x, v0.y, h[0], l[0]);
    split2(v0.z, v0.w, h[1], l[1]);
    split2(v1.x, v1.y, h[2], l[2]);
    split2(v1.z, v1.w, h[3], l[3]);

    const int r7 = lr & 7;
    unsigned char* rowb = dstbase + ((size_t)ch * rows + lr) * 128;
    *(uint4*)(rowb + ((g ^ r7) << 4))       = make_uint4(h[0], h[1], h[2], h[3]);
    *(uint4*)(rowb + (((g + 4) ^ r7) << 4)) = make_uint4(l[0], l[1], l[2], l[3]);
}

// ---------------------------------------------------------------------------
// Projection: CTA 128M x 64N (halves W L2 re-reads: 196MB -> 148MB), 8 warps
// (2m x 2n... 4m? -> wm = wid>>1 in 0..3 covers 32m each; wn = wid&1 covers 32n),
// warp tile 32m x 32n (R7-proven fragment pattern), cp.async 4-stage x 24KB.
// Grid: 48 mtiles (16 Q + 32 K) x 4... N=256/64 -> 4? No: ntiles = 256/64 = 4
// per matrix; wait N tile = 64 -> 4 ntiles. Grid = 48 * 4 = 192? M=128 halves
// mtiles: Q 16 + K 32 = 48 mtiles, x4 ntiles = 192 CTAs.
// ---------------------------------------------------------------------------
#define PSTAGE 24576       // per stage: 16KB A (128 rows) + 8KB W (64 rows)
#define PROJ_SMEM 98304    // 4 stages
#define STAGE_PITCH 144

__global__ __launch_bounds__(256, 2) void proj_mma()
{
    extern __shared__ char smem_all[];

    const int mtile = blockIdx.x >> 2;     // 0..47
    const int ntile = blockIdx.x & 3;
    int isQ, m0, m0row;
    if (mtile < 16) { isQ = 1; m0 = mtile * 128;        m0row = m0; }
    else            { isQ = 0; m0 = (mtile - 16) * 128; m0row = 2048 + m0; }
    const int n0 = ntile * 64;
    const int wrow = (isQ ? 0 : 256) + n0;

    const int tid  = threadIdx.x;
    const int wid  = tid >> 5;
    const int lane = tid & 31;
    const int wm = wid >> 1;      // 0..3 -> m sub 32
    const int wn = wid & 1;       // 0..1 -> n sub 32

    const uint32_t sm_u = smem_u32(smem_all);

#define PROJ_ISSUE(ch)  do {                                                   \
        const uint32_t st_ = sm_u + ((ch) & 3) * PSTAGE;                       \
        const uint4* sA_ = g_AC + ((size_t)(ch) * 6144 + m0row) * 8;           \
        const uint4* sW_ = g_WC + ((size_t)(ch) * 512  + wrow) * 8;            \
        asm volatile("cp.async.cg.shared.global [%0], [%1], 16;"               \
            :: "r"(st_ + tid * 16),           "l"(sA_ + tid)       : "memory");\
        asm volatile("cp.async.cg.shared.global [%0], [%1], 16;"               \
            :: "r"(st_ + (tid + 256) * 16),   "l"(sA_ + tid + 256) : "memory");\
        asm volatile("cp.async.cg.shared.global [%0], [%1], 16;"               \
            :: "r"(st_ + (tid + 512) * 16),   "l"(sA_ + tid + 512) : "memory");\
        asm volatile("cp.async.cg.shared.global [%0], [%1], 16;"               \
            :: "r"(st_ + (tid + 768) * 16),   "l"(sA_ + tid + 768) : "memory");\
        asm volatile("cp.async.cg.shared.global [%0], [%1], 16;"               \
            :: "r"(st_ + 16384 + tid * 16),         "l"(sW_ + tid) : "memory");\
        asm volatile("cp.async.cg.shared.global [%0], [%1], 16;"               \
            :: "r"(st_ + 16384 + (tid + 256) * 16), "l"(sW_ + tid + 256) : "memory"); \
    } while (0)

    PROJ_ISSUE(0); asm volatile("cp.async.commit_group;");
    PROJ_ISSUE(1); asm volatile("cp.async.commit_group;");
    PROJ_ISSUE(2); asm volatile("cp.async.commit_group;");

    // warp 32m x 32n fragment mapping (R7 pattern)
    const int rowA0 = wm * 32 + (lane & 7) + ((lane >> 3) & 1) * 8;  // mm adds +16
    const int uaddA = (lane >> 4) & 1;
    const int rowB0 = wn * 32 + (lane & 7) + ((lane >> 4) & 1) * 8;  // nsub adds +16
    const int uaddB = (lane >> 3) & 1;
    const int ar7 = rowA0 & 7;
    const int br7 = rowB0 & 7;

    float acc[2][4][4];
#pragma unroll
    for (int mm = 0; mm < 2; mm++)
#pragma unroll
        for (int nn = 0; nn < 4; nn++)
#pragma unroll
            for (int c = 0; c < 4; c++) acc[mm][nn][c] = 0.f;

    for (int ch = 0; ch < 32; ch++) {
        asm volatile("cp.async.wait_group 2;");
        __syncthreads();
        if (ch + 3 < 32) { PROJ_ISSUE(ch + 3); }
        asm volatile("cp.async.commit_group;");

        const uint32_t aB = sm_u + (ch & 3) * PSTAGE;
        const uint32_t bB = aB + 16384;
#pragma unroll
        for (int s = 0; s < 2; s++) {
            const int uHA = s * 2 + uaddA, uLA = uHA + 4;
            const int uHB = s * 2 + uaddB, uLB = uHB + 4;
            uint32_t aH0[4], aH1[4], aL0[4], aL1[4];
            uint32_t bH0[4], bH1[4], bL0[4], bL1[4];
            LDSM4(aH0, aB + rowA0 * 128        + ((uHA ^ ar7) << 4));
            LDSM4(aH1, aB + (rowA0 + 16) * 128 + ((uHA ^ ar7) << 4));
            LDSM4(bH0, bB + rowB0 * 128        + ((uHB ^ br7) << 4));
            LDSM4(bH1, bB + (rowB0 + 16) * 128 + ((uHB ^ br7) << 4));
            LDSM4(aL0, aB + rowA0 * 128        + ((uLA ^ ar7) << 4));
            LDSM4(aL1, aB + (rowA0 + 16) * 128 + ((uLA ^ ar7) << 4));
            LDSM4(bL0, bB + rowB0 * 128        + ((uLB ^ br7) << 4));
            LDSM4(bL1, bB + (rowB0 + 16) * 128 + ((uLB ^ br7) << 4));

            MMA_BF16(acc[0][0], aH0, bH0[0], bH0[1]); MMA_BF16(acc[0][1], aH0, bH0[2], bH0[3]);
            MMA_BF16(acc[0][2], aH0, bH1[0], bH1[1]); MMA_BF16(acc[0][3], aH0, bH1[2], bH1[3]);
            MMA_BF16(acc[1][0], aH1, bH0[0], bH0[1]); MMA_BF16(acc[1][1], aH1, bH0[2], bH0[3]);
            MMA_BF16(acc[1][2], aH1, bH1[0], bH1[1]); MMA_BF16(acc[1][3], aH1, bH1[2], bH1[3]);

            MMA_BF16(acc[0][0], aH0, bL0[0], bL0[1]); MMA_BF16(acc[0][1], aH0, bL0[2], bL0[3]);
            MMA_BF16(acc[0][2], aH0, bL1[0], bL1[1]); MMA_BF16(acc[0][3], aH0, bL1[2], bL1[3]);
            MMA_BF16(acc[1][0], aH1, bL0[0], bL0[1]); MMA_BF16(acc[1][1], aH1, bL0[2], bL0[3]);
            MMA_BF16(acc[1][2], aH1, bL1[0], bL1[1]); MMA_BF16(acc[1][3], aH1, bL1[2], bL1[3]);

            MMA_BF16(acc[0][0], aL0, bH0[0], bH0[1]); MMA_BF16(acc[0][1], aL0, bH0[2], bH0[3]);
            MMA_BF16(acc[0][2], aL0, bH1[0], bH1[1]); MMA_BF16(acc[0][3], aL0, bH1[2], bH1[3]);
            MMA_BF16(acc[1][0], aL1, bH0[0], bH0[1]); MMA_BF16(acc[1][1], aL1, bH0[2], bH0[3]);
            MMA_BF16(acc[1][2], aL1, bH1[0], bH1[1]); MMA_BF16(acc[1][3], aL1, bH1[2], bH1[3]);
        }
    }
    asm volatile("cp.async.wait_group 0;");
    __syncthreads();

    // ---- Stage fragments: rows = head_local(0..1)*128 + local_m, pitch 144 ----
#pragma unroll
    for (int mm = 0; mm < 2; mm++) {
#pragma unroll
        for (int nn = 0; nn < 4; nn++) {
            const int local_n = wn * 32 + nn * 8 + (lane & 3) * 2;
            const int head_local = local_n >> 5;
            const int d0 = local_n & 31;
            const int u = d0 >> 3;
            const int within = (d0 & 7) * 2;
#pragma unroll
            for (int rr = 0; rr < 2; rr++) {
                const int local_m = wm * 32 + mm * 16 + (lane >> 2) + rr * 8;
                uint32_t hv, lv;
                split2(acc[mm][nn][rr * 2], acc[mm][nn][rr * 2 + 1], hv, lv);
                char* rb = smem_all + (head_local * 128 + local_m) * STAGE_PITCH;
                const int r7 = local_m & 7;
                *(uint32_t*)(rb + ((u ^ r7) << 4) + within)       = hv;
                *(uint32_t*)(rb + (((u + 4) ^ r7) << 4) + within) = lv;
            }
        }
    }
    __syncthreads();

    // ---- Coalesced gmem write: 256 rows x 128B, 8 passes ----
    unsigned char* gbase = (unsigned char*)(isQ ? g_Q_sw : g_K_sw);
#pragma unroll
    for (int pass = 0; pass < 8; pass++) {
        const int row = (tid >> 3) + pass * 32;     // 0..255
        const int unit = tid & 7;
        const int head_local = row >> 7;
        const int local_m = row & 127;
        const int m = m0 + local_m;
        const int head = (n0 >> 5) + head_local;
        uint4 v = *(uint4*)(smem_all + row * STAGE_PITCH + unit * 16);
        *(uint4*)(gbase + (size_t)(m * 8 + head) * 128 + unit * 16) = v;
    }
}

// ---------------------------------------------------------------------------
// Main kernel (R15 pipeline config; epilogue MLP restructured for ILP —
// identical FP summation order, 8-wide parallel chains).
// ---------------------------------------------------------------------------
#define MSTAGE   12288
#define SM_RPE   49152
#define SM_QP    53264
#define SM_KP    53392
#define SM_TOT   53648

__global__ __launch_bounds__(256, 3) void rpe_gate_mma(
    const int*   __restrict__ qpos, const int* __restrict__ kpos,
    const float* __restrict__ rpe_table,
    const float* __restrict__ w1, const float* __restrict__ b1,
    const float* __restrict__ w2, const float* __restrict__ b2,
    float* __restrict__ out)
{
    extern __shared__ char sm[];
    const uint32_t sb = smem_u32(sm);

    const int tid  = threadIdx.x;
    const int wid  = tid >> 5;
    const int lane = tid & 31;
    const int ktile = blockIdx.x;
    const int qtile = blockIdx.y;

    const int lr_k = tid >> 3;
    const int lu   = tid & 7;
#define MAIN_ISSUE(h) do {                                                     \
        const uint32_t st_ = sb + ((h) & 3) * MSTAGE;                          \
        const uint4* bK_ = g_K_sw + ((size_t)(ktile * 64) * 8 + (h)) * 8;      \
        const uint4* bQ_ = g_Q_sw + ((size_t)(qtile * 32) * 8 + (h)) * 8;      \
        asm volatile("cp.async.cg.shared.global [%0], [%1], 16;"               \
            :: "r"(st_ + tid * 16),                                            \
               "l"(bK_ + (size_t)lr_k * 64 + lu) : "memory");                  \
        asm volatile("cp.async.cg.shared.global [%0], [%1], 16;"               \
            :: "r"(st_ + (tid + 256) * 16),                                    \
               "l"(bK_ + (size_t)(lr_k + 32) * 64 + lu) : "memory");           \
        asm volatile("cp.async.cg.shared.global [%0], [%1], 16;"               \
            :: "r"(st_ + 8192 + tid * 16),                                     \
               "l"(bQ_ + (size_t)lr_k * 64 + lu) : "memory");                  \
    } while (0)

    MAIN_ISSUE(0); asm volatile("cp.async.commit_group;");
    MAIN_ISSUE(1); asm volatile("cp.async.commit_group;");
    MAIN_ISSUE(2); asm volatile("cp.async.commit_group;");

    for (int i = tid; i < 257; i += 256)
        *(float4*)(sm + SM_RPE + i * 16) = ((const float4*)rpe_table)[i];
    if (tid < 32) *(int*)(sm + SM_QP + tid * 4) = qpos[qtile * 32 + tid];
    if (tid < 64) *(int*)(sm + SM_KP + tid * 4) = kpos[ktile * 64 + tid];

    const int wk0 = (wid & 3) * 16;
    const int wq0 = (wid >> 2) * 16;

    const int rowA = wk0 + (lane & 7) + ((lane >> 3) & 1) * 8;
    const int uaddA = (lane >> 4) & 1;
    const int rowB = wq0 + (lane & 7) + ((lane >> 4) & 1) * 8;
    const int uaddB = (lane >> 3) & 1;
    const int ar7 = rowA & 7;
    const int br7 = rowB & 7;

    float acc[8][2][4];
#pragma unroll
    for (int h = 0; h < 8; h++)
#pragma unroll
        for (int j = 0; j < 2; j++)
#pragma unroll
            for (int c = 0; c < 4; c++) acc[h][j][c] = 0.f;

#pragma unroll
    for (int h = 0; h < 8; h++) {
        asm volatile("cp.async.wait_group 2;");
        __syncthreads();
        if (h + 3 < 8) { MAIN_ISSUE(h + 3); }
        asm volatile("cp.async.commit_group;");

        const uint32_t stg = sb + (h & 3) * MSTAGE;
        const uint32_t ah = stg + rowA * 128;
        const uint32_t bh = stg + 8192 + rowB * 128;
#pragma unroll
        for (int s = 0; s < 2; s++) {
            const int uHiA = s * 2 + uaddA, uLoA = uHiA + 4;
            const int uHiB = s * 2 + uaddB, uLoB = uHiB + 4;
            uint32_t aH[4], aL[4], bH[4], bL[4];
            LDSM4(aH, ah + ((uHiA ^ ar7) << 4));
            LDSM4(bH, bh + ((uHiB ^ br7) << 4));
            LDSM4(aL, ah + ((uLoA ^ ar7) << 4));
            LDSM4(bL, bh + ((uLoB ^ br7) << 4));
            MMA_BF16(acc[h][0], aH, bH[0], bH[1]);
            MMA_BF16(acc[h][1], aH, bH[2], bH[3]);
            MMA_BF16(acc[h][0], aH, bL[0], bL[1]);
            MMA_BF16(acc[h][1], aH, bL[2], bL[3]);
            MMA_BF16(acc[h][0], aL, bH[0], bH[1]);
            MMA_BF16(acc[h][1], aL, bH[2], bH[3]);
        }
    }
    asm volatile("cp.async.wait_group 0;");

    // ---- Epilogue (same math/order, ILP-restructured MLP loops) ----
    float w1r[8][4], b1r[8], w2r[4][8], b2r[4];
#pragma unroll
    for (int e = 0; e < 8; e++) {
        b1r[e] = __ldg(&b1[e]);
#pragma unroll
        for (int h = 0; h < 4; h++) w1r[e][h] = __ldg(&w1[e * 4 + h]);
    }
#pragma unroll
    for (int h = 0; h < 4; h++) {
        b2r[h] = __ldg(&b2[h]);
#pragma unroll
        for (int e = 0; e < 8; e++) w2r[h][e] = __ldg(&w2[h * 8 + e]);
    }

    const float4* rpe_s = (const float4*)(sm + SM_RPE);
    const int* qp_s = (const int*)(sm + SM_QP);
    const int* kp_s = (const int*)(sm + SM_KP);

    const int krow0 = wk0 + (lane >> 2);
    const int qcol0 = wq0 + (lane & 3) * 2;
    const int kg0 = ktile * 64;
    const int qg0 = qtile * 32;

    int kv[2], qv[2][2];
#pragma unroll
    for (int kr = 0; kr < 2; kr++) kv[kr] = kp_s[krow0 + kr * 8];
#pragma unroll
    for (int j = 0; j < 2; j++)
#pragma unroll
        for (int qc = 0; qc < 2; qc++) qv[j][qc] = qp_s[qcol0 + j * 8 + qc];

#pragma unroll
    for (int j = 0; j < 2; j++) {
#pragma unroll
        for (int kr = 0; kr < 2; kr++) {
#pragma unroll
            for (int qc = 0; qc < 2; qc++) {
                const int c = kr * 2 + qc;
                int rel = qv[j][qc] - kv[kr];
                rel = rel < -128 ? -128 : (rel > 128 ? 128 : rel);
                float4 rp = rpe_s[rel + 128];
                float rph[4] = {rp.x, rp.y, rp.z, rp.w};

                float sh[4], gh[4];
#pragma unroll
                for (int h = 0; h < 4; h++) {
                    sh[h] = fmaxf(acc[h][j][c] + rph[h], 0.f);
                    gh[h] = acc[4 + h][j][c] + rph[h];
                }
                // Layer 1: 8 parallel accumulation chains (same h-order per t[e])
                float t[8];
#pragma unroll
                for (int e = 0; e < 8; e++) t[e] = b1r[e];
#pragma unroll
                for (int h = 0; h < 4; h++)
#pragma unroll
                    for (int e = 0; e < 8; e++)
                        t[e] = fmaf(gh[h], w1r[e][h], t[e]);
#pragma unroll
                for (int e = 0; e < 8; e++) t[e] = fmaxf(t[e], 0.f);
                // Layer 2: 4 parallel chains (same e-order per zh[h])
                float zh[4] = {b2r[0], b2r[1], b2r[2], b2r[3]};
#pragma unroll
                for (int e = 0; e < 8; e++)
#pragma unroll
                    for (int h = 0; h < 4; h++)
                        zh[h] = fmaf(t[e], w2r[h][e], zh[h]);
                float o = 0.f;
#pragma unroll
                for (int h = 0; h < 4; h++) {
                    float g = __fdividef(1.f, 1.f + __expf(-zh[h]));
                    o = fmaf(sh[h], g, o);
                }
                const int qg = qg0 + qcol0 + j * 8 + qc;
                const int kg = kg0 + krow0 + kr * 8;
                out[(size_t)qg * NK + kg] = o;
            }
        }
    }
}

// ---------------------------------------------------------------------------
extern "C" void kernel_launch(void* const* d_in, const int* in_sizes, int n_in,
                              void* d_out, int out_size)
{
    const float* query = (const float*)d_in[0];
    const float* key   = (const float*)d_in[1];
    const int*   qpos  = (const int*)  d_in[2];
    const int*   kpos  = (const int*)  d_in[3];
    const float* Wq    = (const float*)d_in[4];
    const float* Wk    = (const float*)d_in[5];
    const float* rpe   = (const float*)d_in[6];
    const float* w1    = (const float*)d_in[7];
    const float* b1    = (const float*)d_in[8];
    const float* w2    = (const float*)d_in[9];
    const float* b2    = (const float*)d_in[10];
    float* out = (float*)d_out;
    (void)in_sizes; (void)n_in; (void)out_size;

    cudaFuncSetAttribute(proj_mma,
                         cudaFuncAttributeMaxDynamicSharedMemorySize, PROJ_SMEM);
    cudaFuncSetAttribute(rpe_gate_mma,
                         cudaFuncAttributeMaxDynamicSharedMemorySize, SM_TOT);

    convert_split<<<3328, 256>>>(query, key, Wq, Wk);
    proj_mma<<<192, 256, PROJ_SMEM>>>();
    rpe_gate_mma<<<dim3(NK / 64, NQ / 32), 256, SM_TOT>>>(
        qpos, kpos, rpe, w1, b1, w2, b2, out);
}

// round 17
// speedup vs baseline: 1.3085x; 1.3085x over previous
#include <cuda_runtime.h>
#include <cuda_bf16.h>
#include <cuda_fp16.h>
#include <cstdint>

#define NQ 2048
#define NK 4096
#define DIMK 1024

// fp16 operand tiles for the main kernel: per (pos, head-pair hp) one 128B row
// = head 2hp d0..31 fp16 | head 2hp+1 d0..31, 16B units permuted u ^= (pos&7).
__device__ uint4 g_K16[NK * 4 * 8];   // (pos*4+hp)*8 units, 2 MB
__device__ uint4 g_Q16[NQ * 4 * 8];   // 1 MB

// Pre-converted projection operands (bf16 hi|lo split), chunked layout.
__device__ uint4 g_AC[32 * 6144 * 8];   // 25.2 MB
__device__ uint4 g_WC[32 * 512 * 8];    // 2 MB

#define LDSM4(r, addr) \
    asm volatile("ldmatrix.sync.aligned.m8n8.x4.shared.b16 {%0,%1,%2,%3}, [%4];" \
        : "=r"((r)[0]),"=r"((r)[1]),"=r"((r)[2]),"=r"((r)[3]) : "r"(addr))

#define MMA_BF16(accp, a, b0, b1) \
    asm volatile("mma.sync.aligned.m16n8k16.row.col.f32.bf16.bf16.f32 " \
        "{%0,%1,%2,%3}, {%4,%5,%6,%7}, {%8,%9}, {%0,%1,%2,%3};" \
        : "+f"((accp)[0]),"+f"((accp)[1]),"+f"((accp)[2]),"+f"((accp)[3]) \
        : "r"((a)[0]),"r"((a)[1]),"r"((a)[2]),"r"((a)[3]), "r"(b0),"r"(b1))

#define MMA_F16(accp, a, b0, b1) \
    asm volatile("mma.sync.aligned.m16n8k16.row.col.f32.f16.f16.f32 " \
        "{%0,%1,%2,%3}, {%4,%5,%6,%7}, {%8,%9}, {%0,%1,%2,%3};" \
        : "+f"((accp)[0]),"+f"((accp)[1]),"+f"((accp)[2]),"+f"((accp)[3]) \
        : "r"((a)[0]),"r"((a)[1]),"r"((a)[2]),"r"((a)[3]), "r"(b0),"r"(b1))

static __device__ __forceinline__ uint32_t smem_u32(const void* p) {
    uint32_t a;
    asm("{ .reg .u64 t; cvta.to.shared.u64 t, %1; cvt.u32.u64 %0, t; }"
        : "=r"(a) : "l"(p));
    return a;
}

static __device__ __forceinline__ void split2(float f0, float f1,
                                              uint32_t& hv, uint32_t& lv) {
    __nv_bfloat16 h0 = __float2bfloat16(f0);
    __nv_bfloat16 h1 = __float2bfloat16(f1);
    __nv_bfloat16 l0 = __float2bfloat16(f0 - __bfloat162float(h0));
    __nv_bfloat16 l1 = __float2bfloat16(f1 - __bfloat162float(h1));
    hv = (uint32_t)__bfloat16_as_ushort(h0) | ((uint32_t)__bfloat16_as_ushort(h1) << 16);
    lv = (uint32_t)__bfloat16_as_ushort(l0) | ((uint32_t)__bfloat16_as_ushort(l1) << 16);
}

// ---------------------------------------------------------------------------
// Convert kernel (unchanged): fp32 -> bf16 hi|lo split chunks for proj.
// ---------------------------------------------------------------------------
__global__ __launch_bounds__(256) void convert_split(
    const float* __restrict__ Qin, const float* __restrict__ Kin,
    const float* __restrict__ Wq,  const float* __restrict__ Wk)
{
    const int t = blockIdx.x * 256 + threadIdx.x;
    const int r = t >> 7;
    const int rem = t & 127;
    const int ch = rem >> 2;
    const int g  = rem & 3;

    const float* src;
    unsigned char* dstbase;
    int rows, lr;
    if (r < 6144) {
        lr = r;
        src = (r < 2048) ? (Qin + (size_t)r * DIMK)
                         : (Kin + (size_t)(r - 2048) * DIMK);
        dstbase = (unsigned char*)g_AC; rows = 6144;
    } else {
        lr = r - 6144;
        src = (lr < 256) ? (Wq + (size_t)lr * DIMK)
                         : (Wk + (size_t)(lr - 256) * DIMK);
        dstbase = (unsigned char*)g_WC; rows = 512;
    }

    const float* p = src + ch * 32 + g * 8;
    float4 v0 = *(const float4*)p;
    float4 v1 = *(const float4*)(p + 4);

    uint32_t h[4], l[4];
    split2(v0.x, v0.y, h[0], l[0]);
    split2(v0.z, v0.w, h[1], l[1]);
    split2(v1.x, v1.y, h[2], l[2]);
    split2(v1.z, v1.w, h[3], l[3]);

    const int r7 = lr & 7;
    unsigned char* rowb = dstbase + ((size_t)ch * rows + lr) * 128;
    *(uint4*)(rowb + ((g ^ r7) << 4))       = make_uint4(h[0], h[1], h[2], h[3]);
    *(uint4*)(rowb + (((g + 4) ^ r7) << 4)) = make_uint4(l[0], l[1], l[2], l[3]);
}

// ---------------------------------------------------------------------------
// Projection (R15 mainloop): CTA 64M x 64N, 8 warps (2m x 4n), warp 32x16,
// cp.async 4-stage pipeline, bf16-split 3-term GEMM (full precision).
// Epilogue NEW: fp32 -> single fp16, staged + coalesced into g_{Q,K}16
// head-pair layout (64N tile == exactly one head pair).
// ---------------------------------------------------------------------------
#define PSTAGE 16384
#define PROJ_SMEM 65536
#define STAGE_PITCH 144

__global__ __launch_bounds__(256, 3) void proj_mma()
{
    extern __shared__ char smem_all[];

    const int mtile = blockIdx.x >> 2;     // 0..95
    const int ntile = blockIdx.x & 3;
    int isQ, m0, m0row;
    if (mtile < 32) { isQ = 1; m0 = mtile * 64;        m0row = m0; }
    else            { isQ = 0; m0 = (mtile - 32) * 64; m0row = 2048 + m0; }
    const int n0 = ntile * 64;
    const int wrow = (isQ ? 0 : 256) + n0;

    const int tid  = threadIdx.x;
    const int wid  = tid >> 5;
    const int lane = tid & 31;
    const int wm = wid & 1;
    const int wn = wid >> 1;

    const uint32_t sm_u = smem_u32(smem_all);

#define PROJ_ISSUE(ch)  do {                                                   \
        const uint32_t st_ = sm_u + ((ch) & 3) * PSTAGE;                       \
        const uint4* sA_ = g_AC + ((size_t)(ch) * 6144 + m0row) * 8;           \
        const uint4* sW_ = g_WC + ((size_t)(ch) * 512  + wrow) * 8;            \
        asm volatile("cp.async.cg.shared.global [%0], [%1], 16;"               \
            :: "r"(st_ + tid * 16),          "l"(sA_ + tid)       : "memory"); \
        asm volatile("cp.async.cg.shared.global [%0], [%1], 16;"               \
            :: "r"(st_ + (tid + 256) * 16),  "l"(sA_ + tid + 256) : "memory"); \
        asm volatile("cp.async.cg.shared.global [%0], [%1], 16;"               \
            :: "r"(st_ + 8192 + tid * 16),         "l"(sW_ + tid) : "memory"); \
        asm volatile("cp.async.cg.shared.global [%0], [%1], 16;"               \
            :: "r"(st_ + 8192 + (tid + 256) * 16), "l"(sW_ + tid + 256) : "memory"); \
    } while (0)

    PROJ_ISSUE(0); asm volatile("cp.async.commit_group;");
    PROJ_ISSUE(1); asm volatile("cp.async.commit_group;");
    PROJ_ISSUE(2); asm volatile("cp.async.commit_group;");

    const int rowA0 = wm * 32 + (lane & 7) + ((lane >> 3) & 1) * 8;
    const int uaddA = (lane >> 4) & 1;
    const int rowB0 = wn * 16 + (lane & 7) + ((lane >> 4) & 1) * 8;
    const int uaddB = (lane >> 3) & 1;
    const int ar7 = rowA0 & 7;
    const int br7 = rowB0 & 7;

    float acc[2][2][4];
#pragma unroll
    for (int mm = 0; mm < 2; mm++)
#pragma unroll
        for (int nn = 0; nn < 2; nn++)
#pragma unroll
            for (int c = 0; c < 4; c++) acc[mm][nn][c] = 0.f;

    for (int ch = 0; ch < 32; ch++) {
        asm volatile("cp.async.wait_group 2;");
        __syncthreads();
        if (ch + 3 < 32) { PROJ_ISSUE(ch + 3); }
        asm volatile("cp.async.commit_group;");

        const uint32_t aB = sm_u + (ch & 3) * PSTAGE;
        const uint32_t bB = aB + 8192;
#pragma unroll
        for (int s = 0; s < 2; s++) {
            const int uHA = s * 2 + uaddA, uLA = uHA + 4;
            const int uHB = s * 2 + uaddB, uLB = uHB + 4;
            uint32_t aH0[4], aH1[4], aL0[4], aL1[4], bH[4], bL[4];
            LDSM4(aH0, aB + rowA0 * 128        + ((uHA ^ ar7) << 4));
            LDSM4(aH1, aB + (rowA0 + 16) * 128 + ((uHA ^ ar7) << 4));
            LDSM4(bH,  bB + rowB0 * 128        + ((uHB ^ br7) << 4));
            LDSM4(aL0, aB + rowA0 * 128        + ((uLA ^ ar7) << 4));
            LDSM4(aL1, aB + (rowA0 + 16) * 128 + ((uLA ^ ar7) << 4));
            LDSM4(bL,  bB + rowB0 * 128        + ((uLB ^ br7) << 4));

            MMA_BF16(acc[0][0], aH0, bH[0], bH[1]); MMA_BF16(acc[0][1], aH0, bH[2], bH[3]);
            MMA_BF16(acc[1][0], aH1, bH[0], bH[1]); MMA_BF16(acc[1][1], aH1, bH[2], bH[3]);
            MMA_BF16(acc[0][0], aH0, bL[0], bL[1]); MMA_BF16(acc[0][1], aH0, bL[2], bL[3]);
            MMA_BF16(acc[1][0], aH1, bL[0], bL[1]); MMA_BF16(acc[1][1], aH1, bL[2], bL[3]);
            MMA_BF16(acc[0][0], aL0, bH[0], bH[1]); MMA_BF16(acc[0][1], aL0, bH[2], bH[3]);
            MMA_BF16(acc[1][0], aL1, bH[0], bH[1]); MMA_BF16(acc[1][1], aL1, bH[2], bH[3]);
        }
    }
    asm volatile("cp.async.wait_group 0;");
    __syncthreads();

    // ---- Stage fp16 fragments: 64 rows (local_m) x 128B, pitch 144 ----
#pragma unroll
    for (int mm = 0; mm < 2; mm++) {
#pragma unroll
        for (int nn = 0; nn < 2; nn++) {
            const int local_n = wn * 16 + nn * 8 + (lane & 3) * 2;   // 0..63
            const int par = local_n >> 5;        // head parity within pair
            const int d0 = local_n & 31;
            const int u = par * 4 + (d0 >> 3);   // logical unit 0..7
            const int within = (d0 & 7) * 2;     // byte offset (4B-aligned)
#pragma unroll
            for (int rr = 0; rr < 2; rr++) {
                const int local_m = wm * 32 + mm * 16 + (lane >> 2) + rr * 8;
                __half2 p = __floats2half2_rn(acc[mm][nn][rr * 2],
                                              acc[mm][nn][rr * 2 + 1]);
                uint32_t hv = *(uint32_t*)&p;
                char* rb = smem_all + local_m * STAGE_PITCH;
                *(uint32_t*)(rb + ((u ^ (local_m & 7)) << 4) + within) = hv;
            }
        }
    }
    __syncthreads();

    // ---- Coalesced gmem write: 64 rows x 128B, 2 passes ----
    unsigned char* gbase = (unsigned char*)(isQ ? g_Q16 : g_K16);
    const int hp = n0 >> 6;   // head pair index 0..3
#pragma unroll
    for (int pass = 0; pass < 2; pass++) {
        const int row = (tid >> 3) + pass * 32;   // 0..63
        const int unit = tid & 7;
        const int m = m0 + row;
        uint4 v = *(uint4*)(smem_all + row * STAGE_PITCH + unit * 16);
        *(uint4*)(gbase + (size_t)(m * 4 + hp) * 128 + unit * 16) = v;
    }
}

// ---------------------------------------------------------------------------
// Main kernel: CTA 64k x 32q, 8 warps, warp 16k x 16q. fp16 single-MMA dot.
// 4 head-pair stages (12KB each) via cp.async pipeline; per (pair, s):
// 2 LDSM4 + 2 MMA per parity -> mainloop instructions ~1/2.7 of bf16-split.
// ---------------------------------------------------------------------------
#define MSTAGE   12288     // 8KB K (64 pos, both heads) + 4KB Q (32 pos)
#define SM_RPE   49152
#define SM_QP    53264
#define SM_KP    53392
#define SM_TOT   53648

__global__ __launch_bounds__(256, 3) void rpe_gate_mma(
    const int*   __restrict__ qpos, const int* __restrict__ kpos,
    const float* __restrict__ rpe_table,
    const float* __restrict__ w1, const float* __restrict__ b1,
    const float* __restrict__ w2, const float* __restrict__ b2,
    float* __restrict__ out)
{
    extern __shared__ char sm[];
    const uint32_t sb = smem_u32(sm);

    const int tid  = threadIdx.x;
    const int wid  = tid >> 5;
    const int lane = tid & 31;
    const int ktile = blockIdx.x;
    const int qtile = blockIdx.y;

    const int lr_k = tid >> 3;    // 0..31
    const int lu   = tid & 7;
    // K row (pos p, pair hp) at g_K16 + (p*4+hp)*8 uint4; row stride 32 uint4.
#define MAIN_ISSUE(hp) do {                                                    \
        const uint32_t st_ = sb + ((hp) & 3) * MSTAGE;                         \
        const uint4* bK_ = g_K16 + ((size_t)(ktile * 64) * 4 + (hp)) * 8;      \
        const uint4* bQ_ = g_Q16 + ((size_t)(qtile * 32) * 4 + (hp)) * 8;      \
        asm volatile("cp.async.cg.shared.global [%0], [%1], 16;"               \
            :: "r"(st_ + tid * 16),                                            \
               "l"(bK_ + (size_t)lr_k * 32 + lu) : "memory");                  \
        asm volatile("cp.async.cg.shared.global [%0], [%1], 16;"               \
            :: "r"(st_ + (tid + 256) * 16),                                    \
               "l"(bK_ + (size_t)(lr_k + 32) * 32 + lu) : "memory");           \
        asm volatile("cp.async.cg.shared.global [%0], [%1], 16;"               \
            :: "r"(st_ + 8192 + tid * 16),                                     \
               "l"(bQ_ + (size_t)lr_k * 32 + lu) : "memory");                  \
    } while (0)

    MAIN_ISSUE(0); asm volatile("cp.async.commit_group;");
    MAIN_ISSUE(1); asm volatile("cp.async.commit_group;");
    MAIN_ISSUE(2); asm volatile("cp.async.commit_group;");

    for (int i = tid; i < 257; i += 256)
        *(float4*)(sm + SM_RPE + i * 16) = ((const float4*)rpe_table)[i];
    if (tid < 32) *(int*)(sm + SM_QP + tid * 4) = qpos[qtile * 32 + tid];
    if (tid < 64) *(int*)(sm + SM_KP + tid * 4) = kpos[ktile * 64 + tid];

    const int wk0 = (wid & 3) * 16;
    const int wq0 = (wid >> 2) * 16;

    const int rowA = wk0 + (lane & 7) + ((lane >> 3) & 1) * 8;
    const int uaddA = (lane >> 4) & 1;
    const int rowB = wq0 + (lane & 7) + ((lane >> 4) & 1) * 8;
    const int uaddB = (lane >> 3) & 1;
    const int ar7 = rowA & 7;
    const int br7 = rowB & 7;

    float acc[8][2][4];
#pragma unroll
    for (int h = 0; h < 8; h++)
#pragma unroll
        for (int j = 0; j < 2; j++)
#pragma unroll
            for (int c = 0; c < 4; c++) acc[h][j][c] = 0.f;

#pragma unroll
    for (int hp = 0; hp < 4; hp++) {
        asm volatile("cp.async.wait_group 2;");
        __syncthreads();
        if (hp + 3 < 4) { MAIN_ISSUE(hp + 3); }
        asm volatile("cp.async.commit_group;");

        const uint32_t stg = sb + (hp & 3) * MSTAGE;
        const uint32_t ah = stg + rowA * 128;
        const uint32_t bh = stg + 8192 + rowB * 128;
#pragma unroll
        for (int par = 0; par < 2; par++) {
            const int h = hp * 2 + par;
#pragma unroll
            for (int s = 0; s < 2; s++) {
                const int uA = par * 4 + s * 2 + uaddA;
                const int uB = par * 4 + s * 2 + uaddB;
                uint32_t aF[4], bF[4];
                LDSM4(aF, ah + ((uA ^ ar7) << 4));
                LDSM4(bF, bh + ((uB ^ br7) << 4));
                MMA_F16(acc[h][0], aF, bF[0], bF[1]);
                MMA_F16(acc[h][1], aF, bF[2], bF[3]);
            }
        }
    }
    asm volatile("cp.async.wait_group 0;");

    // ---- Epilogue (R15 form) ----
    float w1r[8][4], b1r[8], w2r[4][8], b2r[4];
#pragma unroll
    for (int e = 0; e < 8; e++) {
        b1r[e] = __ldg(&b1[e]);
#pragma unroll
        for (int h = 0; h < 4; h++) w1r[e][h] = __ldg(&w1[e * 4 + h]);
    }
#pragma unroll
    for (int h = 0; h < 4; h++) {
        b2r[h] = __ldg(&b2[h]);
#pragma unroll
        for (int e = 0; e < 8; e++) w2r[h][e] = __ldg(&w2[h * 8 + e]);
    }

    const float4* rpe_s = (const float4*)(sm + SM_RPE);
    const int* qp_s = (const int*)(sm + SM_QP);
    const int* kp_s = (const int*)(sm + SM_KP);

    const int krow0 = wk0 + (lane >> 2);
    const int qcol0 = wq0 + (lane & 3) * 2;
    const int kg0 = ktile * 64;
    const int qg0 = qtile * 32;

    int kv[2], qv[2][2];
#pragma unroll
    for (int kr = 0; kr < 2; kr++) kv[kr] = kp_s[krow0 + kr * 8];
#pragma unroll
    for (int j = 0; j < 2; j++)
#pragma unroll
        for (int qc = 0; qc < 2; qc++) qv[j][qc] = qp_s[qcol0 + j * 8 + qc];

#pragma unroll
    for (int j = 0; j < 2; j++) {
#pragma unroll
        for (int kr = 0; kr < 2; kr++) {
#pragma unroll
            for (int qc = 0; qc < 2; qc++) {
                const int c = kr * 2 + qc;
                int rel = qv[j][qc] - kv[kr];
                rel = rel < -128 ? -128 : (rel > 128 ? 128 : rel);
                float4 rp = rpe_s[rel + 128];
                float rph[4] = {rp.x, rp.y, rp.z, rp.w};

                float sh[4], gh[4];
#pragma unroll
                for (int h = 0; h < 4; h++) {
                    sh[h] = fmaxf(acc[h][j][c] + rph[h], 0.f);
                    gh[h] = acc[4 + h][j][c] + rph[h];
                }
                float zh[4] = {b2r[0], b2r[1], b2r[2], b2r[3]};
#pragma unroll
                for (int e = 0; e < 8; e++) {
                    float t = b1r[e];
#pragma unroll
                    for (int h = 0; h < 4; h++) t = fmaf(gh[h], w1r[e][h], t);
                    t = fmaxf(t, 0.f);
#pragma unroll
                    for (int h = 0; h < 4; h++) zh[h] = fmaf(t, w2r[h][e], zh[h]);
                }
                float o = 0.f;
#pragma unroll
                for (int h = 0; h < 4; h++) {
                    float g = __fdividef(1.f, 1.f + __expf(-zh[h]));
                    o = fmaf(sh[h], g, o);
                }
                const int qg = qg0 + qcol0 + j * 8 + qc;
                const int kg = kg0 + krow0 + kr * 8;
                out[(size_t)qg * NK + kg] = o;
            }
        }
    }
}

// ---------------------------------------------------------------------------
extern "C" void kernel_launch(void* const* d_in, const int* in_sizes, int n_in,
                              void* d_out, int out_size)
{
    const float* query = (const float*)d_in[0];
    const float* key   = (const float*)d_in[1];
    const int*   qpos  = (const int*)  d_in[2];
    const int*   kpos  = (const int*)  d_in[3];
    const float* Wq    = (const float*)d_in[4];
    const float* Wk    = (const float*)d_in[5];
    const float* rpe   = (const float*)d_in[6];
    const float* w1    = (const float*)d_in[7];
    const float* b1    = (const float*)d_in[8];
    const float* w2    = (const float*)d_in[9];
    const float* b2    = (const float*)d_in[10];
    float* out = (float*)d_out;
    (void)in_sizes; (void)n_in; (void)out_size;

    cudaFuncSetAttribute(proj_mma,
                         cudaFuncAttributeMaxDynamicSharedMemorySize, PROJ_SMEM);
    cudaFuncSetAttribute(rpe_gate_mma,
                         cudaFuncAttributeMaxDynamicSharedMemorySize, SM_TOT);

    convert_split<<<3328, 256>>>(query, key, Wq, Wk);
    proj_mma<<<384, 256, PROJ_SMEM>>>();
    rpe_gate_mma<<<dim3(NK / 64, NQ / 32), 256, SM_TOT>>>(
        qpos, kpos, rpe, w1, b1, w2, b2, out);
}